// round 16
// baseline (speedup 1.0000x reference)
#include <cuda_runtime.h>
#include <cuda_bf16.h>
#include <cstdint>
#include <cstddef>

#define BATCH 4
#define CCH 256
#define NTOK 4096
#define GROUPS 32
#define CPG 8
#define EPSV 1e-6f

typedef __nv_bfloat16 bf16;

// ---------------- scratch ----------------
__device__ uint4 g_qkvb4[(size_t)3 * BATCH * CCH * NTOK / 8];    // q,k,v [tok][ch] bf16
__device__ uint4 g_wb4[4][CCH * CCH / 8];
__device__ float g_biasqkv[3 * CCH];
__device__ float g_gnstat[BATCH * GROUPS * 4 * 2];

// ---------------- asm helpers ----------------
__device__ __forceinline__ uint32_t smem_u32(const void* p) {
    uint32_t a;
    asm("{ .reg .u64 t; cvta.to.shared.u64 t, %1; cvt.u32.u64 %0, t; }"
        : "=r"(a) : "l"(p));
    return a;
}
__device__ __forceinline__ void ldsm4(uint32_t* r, uint32_t a) {
    asm volatile("ldmatrix.sync.aligned.m8n8.x4.shared.b16 {%0,%1,%2,%3}, [%4];"
        : "=r"(r[0]), "=r"(r[1]), "=r"(r[2]), "=r"(r[3]) : "r"(a));
}
__device__ __forceinline__ void ldsm4t(uint32_t* r, uint32_t a) {
    asm volatile("ldmatrix.sync.aligned.m8n8.x4.trans.shared.b16 {%0,%1,%2,%3}, [%4];"
        : "=r"(r[0]), "=r"(r[1]), "=r"(r[2]), "=r"(r[3]) : "r"(a));
}
__device__ __forceinline__ void mma16(float* c, const uint32_t* a,
                                      uint32_t b0, uint32_t b1) {
    asm volatile(
        "mma.sync.aligned.m16n8k16.row.col.f32.bf16.bf16.f32 "
        "{%0,%1,%2,%3}, {%4,%5,%6,%7}, {%8,%9}, {%0,%1,%2,%3};"
        : "+f"(c[0]), "+f"(c[1]), "+f"(c[2]), "+f"(c[3])
        : "r"(a[0]), "r"(a[1]), "r"(a[2]), "r"(a[3]), "r"(b0), "r"(b1));
}
__device__ __forceinline__ void cp16(uint32_t d, const void* s) {
    asm volatile("cp.async.cg.shared.global [%0], [%1], 16;" :: "r"(d), "l"(s));
}
#define CPCOMMIT asm volatile("cp.async.commit_group;" ::: "memory")
#define CPWAIT(n) asm volatile("cp.async.wait_group %0;" :: "n"(n) : "memory")

__device__ __forceinline__ uint32_t packbf(float a, float b) {
    __nv_bfloat162 h = __floats2bfloat162_rn(a, b);
    return *(uint32_t*)&h;
}

// ---------------------------------------------------------------------------
__global__ void convw_kernel(const float* wq, const float* wk,
                             const float* wv, const float* wo,
                             const float* bq, const float* bk, const float* bv,
                             bf16* w0, bf16* w1, bf16* w2, bf16* w3,
                             float* biasqkv) {
    int i = blockIdx.x * 256 + threadIdx.x;
    w0[i] = __float2bfloat16(wq[i]);
    w1[i] = __float2bfloat16(wk[i]);
    w2[i] = __float2bfloat16(wv[i]);
    w3[i] = __float2bfloat16(wo[i]);
    if (i < CCH) {
        biasqkv[i]           = bq[i];
        biasqkv[CCH + i]     = bk[i];
        biasqkv[2 * CCH + i] = bv[i];
    }
}

// ---------------------------------------------------------------------------
__global__ void gn_stats_kernel(const float* __restrict__ x,
                                float* __restrict__ stat) {
    const float4* xp = (const float4*)(x + (size_t)blockIdx.x * 8192);
    int tid = threadIdx.x;
    float s = 0.f, s2 = 0.f;
    #pragma unroll
    for (int i = 0; i < 8; i++) {
        float4 v = xp[tid + i * 256];
        s  += v.x + v.y + v.z + v.w;
        s2 += v.x*v.x + v.y*v.y + v.z*v.z + v.w*v.w;
    }
    __shared__ float sh0[256], sh1[256];
    sh0[tid] = s; sh1[tid] = s2;
    __syncthreads();
    for (int off = 128; off > 0; off >>= 1) {
        if (tid < off) { sh0[tid] += sh0[tid + off]; sh1[tid] += sh1[tid + off]; }
        __syncthreads();
    }
    if (tid == 0) {
        stat[blockIdx.x * 2]     = sh0[0];
        stat[blockIdx.x * 2 + 1] = sh1[0];
    }
}

// ---------------------------------------------------------------------------
// Fused GN-apply + Q/K/V projections, half-pipelined W staging.
// XN [256 ic][128 tok] stride 136 (affine inline). W halves 128 oc x 264,
// double-buffered; invariant: entering half h, pending = {Wh[h+1]}.
// ---------------------------------------------------------------------------
#define XOFF 0u
#define W0OFF 69632u
#define W1OFF 137216u
#define QSMEM 204800

__global__ void __launch_bounds__(256, 1)
qkv3(const float* __restrict__ x, const float* __restrict__ stat,
     const float* __restrict__ gnw, const float* __restrict__ gnb,
     const bf16* __restrict__ w, const float* __restrict__ biasqkv,
     bf16* __restrict__ qkv) {
    extern __shared__ __align__(16) char smem[];
    const int bz = blockIdx.y;
    const int i0 = blockIdx.x * 128;
    const int tid = threadIdx.x;
    const int lane = tid & 31;
    const int wid  = tid >> 5;
    const int g  = lane >> 2;
    const int t  = lane & 3;
    const int l7  = lane & 7;
    const int l15 = lane & 15;
    const int b3 = (lane >> 3) & 1;
    const int b4 = (lane >> 4) & 1;
    const uint32_t su = smem_u32(smem);

    // stage half h (mat = h>>1 via caller, 128 oc rows) into buffer buf
    auto stageWh = [&](int h, int buf) {
        const bf16* src = w + (size_t)(h >> 1) * CCH * CCH +
                          (size_t)(h & 1) * 128 * CCH;
        uint32_t off = buf ? W1OFF : W0OFF;
        #pragma unroll
        for (int i = 0; i < 16; i++) {
            int cc = tid + i * 256;
            int r = cc >> 5, c8 = cc & 31;
            cp16(su + off + (uint32_t)(r * 264 + c8 * 8) * 2,
                 src + (size_t)r * CCH + c8 * 8);
        }
        CPCOMMIT;
    };

    stageWh(0, 0);

    // ---- GN affine + stage XN (thread owns ic row tid) ----
    {
        int r = tid;
        int bg = bz * GROUPS + (r >> 3);
        float s  = stat[bg*8+0] + stat[bg*8+2] + stat[bg*8+4] + stat[bg*8+6];
        float s2 = stat[bg*8+1] + stat[bg*8+3] + stat[bg*8+5] + stat[bg*8+7];
        const float nall = (float)(CPG * NTOK);
        float mean = s / nall;
        float var  = s2 / nall - mean * mean;
        float rstd = rsqrtf(var + EPSV);
        float sc = rstd * gnw[r];
        float sb = gnb[r] - mean * sc;
        const float4* xp = (const float4*)(x + (size_t)bz * CCH * NTOK +
                                           (size_t)r * NTOK + i0);
        bf16* dst = (bf16*)smem + r * 136;
        #pragma unroll
        for (int c = 0; c < 32; c += 2) {
            float4 v0 = xp[c], v1 = xp[c + 1];
            uint4 u;
            u.x = packbf(v0.x * sc + sb, v0.y * sc + sb);
            u.y = packbf(v0.z * sc + sb, v0.w * sc + sb);
            u.z = packbf(v1.x * sc + sb, v1.y * sc + sb);
            u.w = packbf(v1.z * sc + sb, v1.w * sc + sb);
            *(uint4*)(dst + c * 4) = u;
        }
    }
    stageWh(1, 1);
    CPWAIT(1);          // Wh0 ready
    __syncthreads();    // + XN visible

    for (int h = 0; h < 6; h++) {
        const int mat = h >> 1;
        const int half = h & 1;
        const uint32_t wb = (h & 1) ? W1OFF : W0OFF;

        float acc[16][4];
        #pragma unroll
        for (int b = 0; b < 16; b++)
            #pragma unroll
            for (int qq = 0; qq < 4; qq++) acc[b][qq] = 0.f;

        #pragma unroll
        for (int ks = 0; ks < 16; ks++) {
            uint32_t a2[4];
            ldsm4(a2, su + wb + 2u * (uint32_t)(
                (wid * 16 + l15) * 264 + ks * 16 + b4 * 8));
            #pragma unroll
            for (int j2 = 0; j2 < 8; j2++) {
                uint32_t bfr[4];
                ldsm4t(bfr, su + XOFF + 2u * (uint32_t)(
                    (ks * 16 + b3 * 8 + l7) * 136 + j2 * 16 + b4 * 8));
                mma16(acc[2*j2],     a2, bfr[0], bfr[1]);
                mma16(acc[2*j2 + 1], a2, bfr[2], bfr[3]);
            }
        }

        // write out [tok][oc] bf16
        bf16* C = qkv + (size_t)mat * BATCH * NTOK * CCH + (size_t)bz * NTOK * CCH;
        const float osc = (mat == 0) ? 0.0625f : 1.0f;
        {
            int m = half * 128 + wid * 16 + g;
            float bm0 = biasqkv[mat * CCH + m];
            float bm1 = biasqkv[mat * CCH + m + 8];
            #pragma unroll
            for (int b = 0; b < 16; b++) {
                int n = i0 + b * 8 + 2 * t;
                C[(size_t)n * CCH + m]           = __float2bfloat16((acc[b][0] + bm0) * osc);
                C[(size_t)(n + 1) * CCH + m]     = __float2bfloat16((acc[b][1] + bm0) * osc);
                C[(size_t)n * CCH + m + 8]       = __float2bfloat16((acc[b][2] + bm1) * osc);
                C[(size_t)(n + 1) * CCH + m + 8] = __float2bfloat16((acc[b][3] + bm1) * osc);
            }
        }

        if (h < 5) {
            __syncthreads();                 // this W buffer's reads done
            if (h + 2 < 6) {
                stageWh(h + 2, h & 1);       // refill this buffer
                CPWAIT(1);                   // completes Wh[h+1]
            } else {
                CPWAIT(0);                   // h==4: completes Wh5
            }
            __syncthreads();
        }
    }
}

// ---------------------------------------------------------------------------
// Fused attention + output projection + residual. 2D warp tiling + P smem.
// 2 syncs + 1 CPWAIT per iter. Invariant: entering iter j, pending={K[j],V[j]}.
// ---------------------------------------------------------------------------
#define QOFF  0u
#define K0OFF 67584u
#define K1OFF 101376u
#define V0OFF 135168u
#define V1OFF 168960u
#define POFF  202752u
#define SUMOFF 221184u
#define FSMEM  222208

__global__ void __launch_bounds__(256, 1)
fattn(const bf16* __restrict__ q, const bf16* __restrict__ k,
      const bf16* __restrict__ vt, const bf16* __restrict__ wo,
      const float* __restrict__ bo, const float* __restrict__ x,
      float* __restrict__ out) {
    extern __shared__ __align__(16) char smem[];
    const int bz = blockIdx.y;
    const int i0 = blockIdx.x * 128;
    q   += (size_t)bz * NTOK * CCH;
    k   += (size_t)bz * NTOK * CCH;
    vt  += (size_t)bz * NTOK * CCH;
    x   += (size_t)bz * CCH * NTOK;
    out += (size_t)bz * CCH * NTOK;

    const int tid = threadIdx.x;
    const int lane = tid & 31;
    const int wid  = tid >> 5;
    const int wm = wid >> 1;
    const int wn = wid & 1;
    const int g  = lane >> 2;
    const int t  = lane & 3;
    const int l7  = lane & 7;
    const int l15 = lane & 15;
    const int b3 = (lane >> 3) & 1;
    const int b4 = (lane >> 4) & 1;
    const uint32_t su = smem_u32(smem);

    float O[2][16][4];
    #pragma unroll
    for (int i = 0; i < 2; i++)
        #pragma unroll
        for (int b = 0; b < 16; b++)
            #pragma unroll
            for (int qq = 0; qq < 4; qq++) O[i][b][qq] = 0.f;
    float rs[2][2] = {{0.f, 0.f}, {0.f, 0.f}};

    auto stageQ = [&]() {
        #pragma unroll
        for (int i = 0; i < 16; i++) {
            int cc = tid + i * 256;
            int r = cc >> 5, c8 = cc & 31;
            cp16(su + QOFF + (uint32_t)(r * 264 + c8 * 8) * 2,
                 q + (size_t)(i0 + r) * CCH + c8 * 8);
        }
    };
    auto stage64 = [&](uint32_t off, const bf16* src, int j) {
        #pragma unroll
        for (int i = 0; i < 8; i++) {
            int cc = tid + i * 256;
            int r = cc >> 5, c8 = cc & 31;
            cp16(su + off + (uint32_t)(r * 264 + c8 * 8) * 2,
                 src + (size_t)(j * 64 + r) * CCH + c8 * 8);
        }
    };
    auto stageWo = [&]() {
        const uint32_t bases[4] = {K0OFF, K1OFF, V0OFF, V1OFF};
        #pragma unroll
        for (int i = 0; i < 32; i++) {
            int cc = tid + i * 256;
            int r = cc >> 5, c8 = cc & 31;
            cp16(su + bases[r >> 6] + (uint32_t)((r & 63) * 264 + c8 * 8) * 2,
                 wo + (size_t)r * CCH + c8 * 8);
        }
    };

    stageQ();                CPCOMMIT;
    stage64(K0OFF, k, 0);    CPCOMMIT;
    stage64(V0OFF, vt, 0);   CPCOMMIT;
    // pending: {Q, K0, V0}

    bf16* Ps = (bf16*)(smem + POFF);

    for (int j = 0; j < 64; j++) {
        const uint32_t kb = su + ((j & 1) ? K1OFF : K0OFF);
        const uint32_t vb = su + ((j & 1) ? V1OFF : V0OFF);

        CPWAIT(0);            // completes K[j] and V[j] (and Q at j=0)
        __syncthreads();

        // ---- MMA1: S[32 rows][32 jtok] per warp ----
        float S[2][4][4];
        #pragma unroll
        for (int i = 0; i < 2; i++)
            #pragma unroll
            for (int s = 0; s < 4; s++)
                #pragma unroll
                for (int qq = 0; qq < 4; qq++) S[i][s][qq] = 0.f;

        #pragma unroll
        for (int ks = 0; ks < 16; ks++) {
            uint32_t a[2][4];
            #pragma unroll
            for (int i = 0; i < 2; i++)
                ldsm4(a[i], su + QOFF + 2u * (uint32_t)(
                    (wm * 32 + i * 16 + l15) * 264 + ks * 16 + b4 * 8));
            #pragma unroll
            for (int j2 = 0; j2 < 2; j2++) {
                uint32_t bfr[4];
                ldsm4(bfr, kb + 2u * (uint32_t)(
                    (wn * 32 + j2 * 16 + b4 * 8 + l7) * 264 + ks * 16 + b3 * 8));
                #pragma unroll
                for (int i = 0; i < 2; i++) {
                    mma16(S[i][2*j2],     a[i], bfr[0], bfr[1]);
                    mma16(S[i][2*j2 + 1], a[i], bfr[2], bfr[3]);
                }
            }
        }

        // ---- exp -> P smem + row-sum partials ----
        #pragma unroll
        for (int i = 0; i < 2; i++) {
            int ml = wm * 32 + i * 16 + g;
            #pragma unroll
            for (int s = 0; s < 4; s++) {
                int nl = wn * 32 + s * 8 + 2 * t;
                float e0 = __expf(S[i][s][0]);
                float e1 = __expf(S[i][s][1]);
                float e2 = __expf(S[i][s][2]);
                float e3 = __expf(S[i][s][3]);
                rs[i][0] += e0 + e1;
                rs[i][1] += e2 + e3;
                *(__nv_bfloat162*)(Ps + ml * 72 + nl)       = __floats2bfloat162_rn(e0, e1);
                *(__nv_bfloat162*)(Ps + (ml + 8) * 72 + nl) = __floats2bfloat162_rn(e2, e3);
            }
        }
        __syncthreads();      // P visible (K/V j+1 go to opposite buffers: no WAR)

        if (j < 63) {
            stage64((j & 1) ? K0OFF : K1OFF, k, j + 1);
            CPCOMMIT;
            stage64((j & 1) ? V0OFF : V1OFF, vt, j + 1);
            CPCOMMIT;         // pending: {K[j+1], V[j+1]}
        }

        // ---- MMA2: O += P · V (V[j] completed at top CPWAIT) ----
        #pragma unroll
        for (int ks2 = 0; ks2 < 4; ks2++) {
            uint32_t pa[2][4];
            #pragma unroll
            for (int i = 0; i < 2; i++)
                ldsm4(pa[i], su + POFF + 2u * (uint32_t)(
                    (wm * 32 + i * 16 + l15) * 72 + ks2 * 16 + b4 * 8));
            #pragma unroll
            for (int j2 = 0; j2 < 8; j2++) {
                uint32_t bfr[4];
                ldsm4t(bfr, vb + 2u * (uint32_t)(
                    (ks2 * 16 + b3 * 8 + l7) * 264 + wn * 128 + j2 * 16 + b4 * 8));
                #pragma unroll
                for (int i = 0; i < 2; i++) {
                    mma16(O[i][2*j2],     pa[i], bfr[0], bfr[1]);
                    mma16(O[i][2*j2 + 1], pa[i], bfr[2], bfr[3]);
                }
            }
        }
    }

    __syncthreads();          // all K/V reads done before Wo overwrites
    stageWo();
    CPCOMMIT;

    // ---- row sums -> inverse ----
    float* ps = (float*)(smem + SUMOFF);
    #pragma unroll
    for (int i = 0; i < 2; i++) {
        float s0 = rs[i][0], s1 = rs[i][1];
        s0 += __shfl_xor_sync(0xffffffffu, s0, 1);
        s0 += __shfl_xor_sync(0xffffffffu, s0, 2);
        s1 += __shfl_xor_sync(0xffffffffu, s1, 1);
        s1 += __shfl_xor_sync(0xffffffffu, s1, 2);
        if (t == 0) {
            int r = wm * 32 + i * 16 + g;
            ps[wn * 128 + r]     = s0;
            ps[wn * 128 + r + 8] = s1;
        }
    }
    __syncthreads();
    if (tid < 128) ps[tid] = 1.f / (ps[tid] + ps[128 + tid]);
    __syncthreads();

    // ---- normalize O into Q region ----
    bf16* Os = (bf16*)smem;
    #pragma unroll
    for (int i = 0; i < 2; i++) {
        int r0 = wm * 32 + i * 16 + g;
        int r1 = r0 + 8;
        float iv0 = ps[r0];
        float iv1 = ps[r1];
        #pragma unroll
        for (int b = 0; b < 16; b++) {
            int col = wn * 128 + b * 8 + 2 * t;
            *(__nv_bfloat162*)(Os + r0 * 264 + col) =
                __floats2bfloat162_rn(O[i][b][0] * iv0, O[i][b][1] * iv0);
            *(__nv_bfloat162*)(Os + r1 * 264 + col) =
                __floats2bfloat162_rn(O[i][b][2] * iv1, O[i][b][3] * iv1);
        }
    }
    CPWAIT(0);
    __syncthreads();

    // ---- epilogue GEMM: out[256 co][128 tok] = Wo · Os^T + bo + x ----
    float acc[2][16][4];
    #pragma unroll
    for (int i = 0; i < 2; i++)
        #pragma unroll
        for (int b = 0; b < 16; b++)
            #pragma unroll
            for (int qq = 0; qq < 4; qq++) acc[i][b][qq] = 0.f;

    const uint32_t bases[4] = {K0OFF, K1OFF, V0OFF, V1OFF};
    const uint32_t wo_off = bases[wid >> 1] + (uint32_t)((wid & 1) * 32) * 528;

    #pragma unroll
    for (int ks = 0; ks < 16; ks++) {
        uint32_t a2[2][4];
        #pragma unroll
        for (int i = 0; i < 2; i++)
            ldsm4(a2[i], su + wo_off + 2u * (uint32_t)(
                (i * 16 + l15) * 264 + ks * 16 + b4 * 8));
        #pragma unroll
        for (int j2 = 0; j2 < 8; j2++) {
            uint32_t bfr[4];
            ldsm4(bfr, su + QOFF + 2u * (uint32_t)(
                (j2 * 16 + b4 * 8 + l7) * 264 + ks * 16 + b3 * 8));
            #pragma unroll
            for (int i = 0; i < 2; i++) {
                mma16(acc[i][2*j2],     a2[i], bfr[0], bfr[1]);
                mma16(acc[i][2*j2 + 1], a2[i], bfr[2], bfr[3]);
            }
        }
    }

    #pragma unroll
    for (int i = 0; i < 2; i++) {
        int m = wid * 32 + i * 16 + g;
        float bm0 = bo[m];
        float bm1 = bo[m + 8];
        #pragma unroll
        for (int b = 0; b < 16; b++) {
            int n = i0 + b * 8 + 2 * t;
            float2 x0 = *(const float2*)(x + (size_t)m * NTOK + n);
            float2 x1 = *(const float2*)(x + (size_t)(m + 8) * NTOK + n);
            float2 v0, v1;
            v0.x = acc[i][b][0] + bm0 + x0.x;
            v0.y = acc[i][b][1] + bm0 + x0.y;
            v1.x = acc[i][b][2] + bm1 + x1.x;
            v1.y = acc[i][b][3] + bm1 + x1.y;
            *(float2*)(out + (size_t)m * NTOK + n)       = v0;
            *(float2*)(out + (size_t)(m + 8) * NTOK + n) = v1;
        }
    }
}

// ---------------------------------------------------------------------------
extern "C" void kernel_launch(void* const* d_in, const int* in_sizes, int n_in,
                              void* d_out, int out_size) {
    const float* x    = (const float*)d_in[0];
    const float* gn_w = (const float*)d_in[1];
    const float* gn_b = (const float*)d_in[2];
    const float* wq   = (const float*)d_in[3];
    const float* bq   = (const float*)d_in[4];
    const float* wk   = (const float*)d_in[5];
    const float* bk   = (const float*)d_in[6];
    const float* wv   = (const float*)d_in[7];
    const float* bv   = (const float*)d_in[8];
    const float* wo   = (const float*)d_in[9];
    const float* bo   = (const float*)d_in[10];
    float* out = (float*)d_out;

    void *p_qkv, *p_w, *p_bias, *p_stat;
    cudaGetSymbolAddress(&p_qkv,  g_qkvb4);
    cudaGetSymbolAddress(&p_w,    g_wb4);
    cudaGetSymbolAddress(&p_bias, g_biasqkv);
    cudaGetSymbolAddress(&p_stat, g_gnstat);

    bf16* qkvb = (bf16*)p_qkv;
    bf16* wqb  = (bf16*)p_w;
    bf16* wob  = wqb + 3 * CCH * CCH;
    float* biasqkv = (float*)p_bias;
    float* stat = (float*)p_stat;

    const size_t SBb = (size_t)CCH * NTOK;
    bf16* qb  = qkvb;
    bf16* kb  = qkvb + BATCH * SBb;
    bf16* vtb = qkvb + 2 * BATCH * SBb;

    cudaFuncSetAttribute(qkv3, cudaFuncAttributeMaxDynamicSharedMemorySize, QSMEM);
    cudaFuncSetAttribute(fattn, cudaFuncAttributeMaxDynamicSharedMemorySize, FSMEM);

    // 0) convert+pack weights / biases
    convw_kernel<<<256, 256>>>(wq, wk, wv, wo, bq, bk, bv,
                               wqb, wqb + CCH*CCH, wqb + 2*CCH*CCH, wob, biasqkv);

    // 1) GroupNorm stats only
    gn_stats_kernel<<<BATCH * GROUPS * 4, 256>>>(x, stat);

    // 2) fused GN-apply + q/k/v projections -> [tok][ch] bf16 (q scaled 1/16)
    qkv3<<<dim3(NTOK/128, BATCH), 256, QSMEM>>>(
        x, stat, gn_w, gn_b, wqb, biasqkv, qkvb);

    // 3) fused attention + output projection + residual -> out fp32
    fattn<<<dim3(NTOK/128, BATCH), 256, FSMEM>>>(qb, kb, vtb, wob, bo, x, out);
}

// round 17
// speedup vs baseline: 1.0484x; 1.0484x over previous
#include <cuda_runtime.h>
#include <cuda_bf16.h>
#include <cstdint>
#include <cstddef>

#define BATCH 4
#define CCH 256
#define NTOK 4096
#define GROUPS 32
#define CPG 8
#define EPSV 1e-6f
#define QSCALE 0.09016844005556021f   // (1/16) * log2(e); exp(s/16)=exp2(s*QSCALE)

typedef __nv_bfloat16 bf16;

// ---------------- scratch ----------------
__device__ uint4 g_xnb4 [(size_t)BATCH * CCH * NTOK / 8];        // GN out bf16 [c][tok]
__device__ uint4 g_qkvb4[(size_t)3 * BATCH * CCH * NTOK / 8];    // q,k,v [tok][ch] bf16
__device__ uint4 g_wb4[4][CCH * CCH / 8];
__device__ float g_biasqkv[3 * CCH];
__device__ float g_gnstat[BATCH * GROUPS * 4 * 2];

// ---------------- asm helpers ----------------
__device__ __forceinline__ uint32_t smem_u32(const void* p) {
    uint32_t a;
    asm("{ .reg .u64 t; cvta.to.shared.u64 t, %1; cvt.u32.u64 %0, t; }"
        : "=r"(a) : "l"(p));
    return a;
}
__device__ __forceinline__ void ldsm4(uint32_t* r, uint32_t a) {
    asm volatile("ldmatrix.sync.aligned.m8n8.x4.shared.b16 {%0,%1,%2,%3}, [%4];"
        : "=r"(r[0]), "=r"(r[1]), "=r"(r[2]), "=r"(r[3]) : "r"(a));
}
__device__ __forceinline__ void ldsm4t(uint32_t* r, uint32_t a) {
    asm volatile("ldmatrix.sync.aligned.m8n8.x4.trans.shared.b16 {%0,%1,%2,%3}, [%4];"
        : "=r"(r[0]), "=r"(r[1]), "=r"(r[2]), "=r"(r[3]) : "r"(a));
}
__device__ __forceinline__ void mma16(float* c, const uint32_t* a,
                                      uint32_t b0, uint32_t b1) {
    asm volatile(
        "mma.sync.aligned.m16n8k16.row.col.f32.bf16.bf16.f32 "
        "{%0,%1,%2,%3}, {%4,%5,%6,%7}, {%8,%9}, {%0,%1,%2,%3};"
        : "+f"(c[0]), "+f"(c[1]), "+f"(c[2]), "+f"(c[3])
        : "r"(a[0]), "r"(a[1]), "r"(a[2]), "r"(a[3]), "r"(b0), "r"(b1));
}
__device__ __forceinline__ void cp16(uint32_t d, const void* s) {
    asm volatile("cp.async.cg.shared.global [%0], [%1], 16;" :: "r"(d), "l"(s));
}
#define CPCOMMIT asm volatile("cp.async.commit_group;" ::: "memory")
#define CPWAIT(n) asm volatile("cp.async.wait_group %0;" :: "n"(n) : "memory")

__device__ __forceinline__ uint32_t packbf(float a, float b) {
    __nv_bfloat162 h = __floats2bfloat162_rn(a, b);
    return *(uint32_t*)&h;
}

// ---------------------------------------------------------------------------
__global__ void convw_kernel(const float* wq, const float* wk,
                             const float* wv, const float* wo,
                             const float* bq, const float* bk, const float* bv,
                             bf16* w0, bf16* w1, bf16* w2, bf16* w3,
                             float* biasqkv) {
    int i = blockIdx.x * 256 + threadIdx.x;
    w0[i] = __float2bfloat16(wq[i]);
    w1[i] = __float2bfloat16(wk[i]);
    w2[i] = __float2bfloat16(wv[i]);
    w3[i] = __float2bfloat16(wo[i]);
    if (i < CCH) {
        biasqkv[i]           = bq[i];
        biasqkv[CCH + i]     = bk[i];
        biasqkv[2 * CCH + i] = bv[i];
    }
}

// ---------------------------------------------------------------------------
__global__ void gn_stats_kernel(const float* __restrict__ x,
                                float* __restrict__ stat) {
    const float4* xp = (const float4*)(x + (size_t)blockIdx.x * 8192);
    int tid = threadIdx.x;
    float s = 0.f, s2 = 0.f;
    #pragma unroll
    for (int i = 0; i < 8; i++) {
        float4 v = xp[tid + i * 256];
        s  += v.x + v.y + v.z + v.w;
        s2 += v.x*v.x + v.y*v.y + v.z*v.z + v.w*v.w;
    }
    __shared__ float sh0[256], sh1[256];
    sh0[tid] = s; sh1[tid] = s2;
    __syncthreads();
    for (int off = 128; off > 0; off >>= 1) {
        if (tid < off) { sh0[tid] += sh0[tid + off]; sh1[tid] += sh1[tid + off]; }
        __syncthreads();
    }
    if (tid == 0) {
        stat[blockIdx.x * 2]     = sh0[0];
        stat[blockIdx.x * 2 + 1] = sh1[0];
    }
}

__global__ void gn_apply_kernel(const float* __restrict__ x,
                                const float* __restrict__ stat,
                                const float* __restrict__ w,
                                const float* __restrict__ b,
                                bf16* __restrict__ xnb) {
    int blk = blockIdx.x;
    int bg  = blk >> 2;
    int grp = bg % GROUPS;
    float s  = stat[bg * 8 + 0] + stat[bg * 8 + 2] +
               stat[bg * 8 + 4] + stat[bg * 8 + 6];
    float s2 = stat[bg * 8 + 1] + stat[bg * 8 + 3] +
               stat[bg * 8 + 5] + stat[bg * 8 + 7];
    const float nall = (float)(CPG * NTOK);
    float mean = s / nall;
    float var  = s2 / nall - mean * mean;
    float rstd = rsqrtf(var + EPSV);

    size_t base = (size_t)blk * 8192;
    const float4* xp = (const float4*)(x + base);
    bf16* op = xnb + base;
    int tid = threadIdx.x;
    #pragma unroll
    for (int i = 0; i < 8; i++) {
        int idx = tid + i * 256;
        int ch = grp * CPG + (int)(((blk & 3) * 8192 + idx * 4) / NTOK);
        float sc = rstd * w[ch];
        float sb = b[ch] - mean * sc;
        float4 v = xp[idx];
        __nv_bfloat162 h0 = __floats2bfloat162_rn(v.x * sc + sb, v.y * sc + sb);
        __nv_bfloat162 h1 = __floats2bfloat162_rn(v.z * sc + sb, v.w * sc + sb);
        uint2 u;
        u.x = *(uint32_t*)&h0; u.y = *(uint32_t*)&h1;
        *(uint2*)(op + idx * 4) = u;
    }
}

// ---------------------------------------------------------------------------
// bf16 GEMM for QKV transposed projections (R14 configuration).
// ---------------------------------------------------------------------------
#define ABYTES 18432u
#define STAGEB 36864u
#define SMEM_DYN (3 * 36864)

__global__ void __launch_bounds__(128, 2)
bgemm_qkv(const bf16* __restrict__ A, const bf16* __restrict__ B,
          const float* __restrict__ bias, void* __restrict__ Cv,
          int lda, size_t sA) {
    extern __shared__ __align__(16) char smem[];
    const int bz = blockIdx.z;

    int mat = blockIdx.y >> 5;
    B    += (size_t)mat * (CCH * CCH);
    bias += mat * CCH;
    size_t cext = (size_t)mat * BATCH * (size_t)NTOK * CCH;
    float osc = (mat == 0) ? QSCALE : 1.0f;
    const int M0 = (blockIdx.y & 31) * 128;
    A += (size_t)bz * sA;

    const int N0 = blockIdx.x * 128;
    const int tid  = threadIdx.x;
    const int lane = tid & 31;
    const int wid  = tid >> 5;
    const int wm = wid >> 1;
    const int wn = wid & 1;
    const int g  = lane >> 2;
    const int t  = lane & 3;
    const int l7  = lane & 7;
    const int b3 = (lane >> 3) & 1;
    const int b4 = (lane >> 4) & 1;

    const uint32_t smem_u = smem_u32(smem);

    float acc[4][8][4];
    #pragma unroll
    for (int i = 0; i < 4; i++)
        #pragma unroll
        for (int j = 0; j < 8; j++)
            #pragma unroll
            for (int q = 0; q < 4; q++) acc[i][j][q] = 0.f;

    const int KT = CCH >> 6;

    auto stage = [&](int kt, int buf) {
        uint32_t ab = smem_u + (uint32_t)buf * STAGEB;
        uint32_t bbs = ab + ABYTES;
        int k0 = kt << 6;
        #pragma unroll
        for (int i = 0; i < 8; i++) {
            int c = tid + i * 128;
            int k = c >> 4, mc = c & 15;
            cp16(ab + (uint32_t)(k * 136 + mc * 8) * 2,
                 A + (size_t)(k0 + k) * lda + M0 + mc * 8);
        }
        #pragma unroll
        for (int i = 0; i < 8; i++) {
            int c = tid + i * 128;
            int n = c >> 3, kc = c & 7;
            cp16(bbs + (uint32_t)(n * 72 + kc * 8) * 2,
                 B + (size_t)(N0 + n) * CCH + k0 + kc * 8);
        }
    };

    stage(0, 0);
    CPCOMMIT;
    stage(1, 1);
    CPCOMMIT;

    for (int kt = 0; kt < KT; kt++) {
        CPWAIT(1);
        __syncthreads();
        if (kt + 2 < KT) stage(kt + 2, (kt + 2) % 3);
        CPCOMMIT;

        uint32_t ab = smem_u + (uint32_t)(kt % 3) * STAGEB;
        uint32_t bbs = ab + ABYTES;

        #pragma unroll
        for (int ks = 0; ks < 4; ks++) {
            uint32_t af[4][4];
            #pragma unroll
            for (int i = 0; i < 4; i++)
                ldsm4t(af[i], ab + 2u * (uint32_t)(
                    (ks * 16 + b4 * 8 + l7) * 136 + wm * 64 + i * 16 + b3 * 8));
            uint32_t bfr[4][4];
            #pragma unroll
            for (int j2 = 0; j2 < 4; j2++) {
                int nb = wn * 64 + j2 * 16;
                ldsm4(bfr[j2], bbs + 2u * (uint32_t)(
                    (nb + b4 * 8 + l7) * 72 + ks * 16 + b3 * 8));
            }
            #pragma unroll
            for (int j2 = 0; j2 < 4; j2++) {
                #pragma unroll
                for (int i = 0; i < 4; i++) {
                    mma16(acc[i][2*j2],     af[i], bfr[j2][0], bfr[j2][1]);
                    mma16(acc[i][2*j2 + 1], af[i], bfr[j2][2], bfr[j2][3]);
                }
            }
        }
    }

    bf16* C = (bf16*)Cv + cext + (size_t)bz * NTOK * CCH;
    #pragma unroll
    for (int i = 0; i < 4; i++) {
        int m = M0 + wm * 64 + i * 16 + g;
        #pragma unroll
        for (int j = 0; j < 8; j++) {
            int n = N0 + wn * 64 + j * 8 + 2 * t;
            float2 bn = *(const float2*)(bias + n);
            *(__nv_bfloat162*)(C + (size_t)m * CCH + n) =
                __floats2bfloat162_rn((acc[i][j][0] + bn.x) * osc,
                                      (acc[i][j][1] + bn.y) * osc);
            *(__nv_bfloat162*)(C + (size_t)(m + 8) * CCH + n) =
                __floats2bfloat162_rn((acc[i][j][2] + bn.x) * osc,
                                      (acc[i][j][3] + bn.y) * osc);
        }
    }
}

// ---------------------------------------------------------------------------
// Fused attention + output projection + residual (R14 schedule, exp2f).
// ---------------------------------------------------------------------------
#define QOFF  0u
#define K0OFF 67584u
#define K1OFF 101376u
#define V0OFF 135168u
#define V1OFF 168960u
#define POFF  202752u
#define SUMOFF 221184u
#define FSMEM  222208

__global__ void __launch_bounds__(256, 1)
fattn(const bf16* __restrict__ q, const bf16* __restrict__ k,
      const bf16* __restrict__ vt, const bf16* __restrict__ wo,
      const float* __restrict__ bo, const float* __restrict__ x,
      float* __restrict__ out) {
    extern __shared__ __align__(16) char smem[];
    const int bz = blockIdx.y;
    const int i0 = blockIdx.x * 128;
    q   += (size_t)bz * NTOK * CCH;
    k   += (size_t)bz * NTOK * CCH;
    vt  += (size_t)bz * NTOK * CCH;
    x   += (size_t)bz * CCH * NTOK;
    out += (size_t)bz * CCH * NTOK;

    const int tid = threadIdx.x;
    const int lane = tid & 31;
    const int wid  = tid >> 5;
    const int wm = wid >> 1;
    const int wn = wid & 1;
    const int g  = lane >> 2;
    const int t  = lane & 3;
    const int l7  = lane & 7;
    const int l15 = lane & 15;
    const int b3 = (lane >> 3) & 1;
    const int b4 = (lane >> 4) & 1;
    const uint32_t su = smem_u32(smem);

    float O[2][16][4];
    #pragma unroll
    for (int i = 0; i < 2; i++)
        #pragma unroll
        for (int b = 0; b < 16; b++)
            #pragma unroll
            for (int qq = 0; qq < 4; qq++) O[i][b][qq] = 0.f;
    float rs[2][2] = {{0.f, 0.f}, {0.f, 0.f}};

    auto stageQ = [&]() {
        #pragma unroll
        for (int i = 0; i < 16; i++) {
            int cc = tid + i * 256;
            int r = cc >> 5, c8 = cc & 31;
            cp16(su + QOFF + (uint32_t)(r * 264 + c8 * 8) * 2,
                 q + (size_t)(i0 + r) * CCH + c8 * 8);
        }
    };
    auto stage64 = [&](uint32_t off, const bf16* src, int j) {
        #pragma unroll
        for (int i = 0; i < 8; i++) {
            int cc = tid + i * 256;
            int r = cc >> 5, c8 = cc & 31;
            cp16(su + off + (uint32_t)(r * 264 + c8 * 8) * 2,
                 src + (size_t)(j * 64 + r) * CCH + c8 * 8);
        }
    };
    auto stageWo = [&]() {
        const uint32_t bases[4] = {K0OFF, K1OFF, V0OFF, V1OFF};
        #pragma unroll
        for (int i = 0; i < 32; i++) {
            int cc = tid + i * 256;
            int r = cc >> 5, c8 = cc & 31;
            cp16(su + bases[r >> 6] + (uint32_t)((r & 63) * 264 + c8 * 8) * 2,
                 wo + (size_t)r * CCH + c8 * 8);
        }
    };

    stageQ();                CPCOMMIT;
    stage64(K0OFF, k, 0);    CPCOMMIT;
    stage64(V0OFF, vt, 0);   CPCOMMIT;
    // pending: {Q, K0, V0}

    bf16* Ps = (bf16*)(smem + POFF);

    for (int j = 0; j < 64; j++) {
        const uint32_t kb = su + ((j & 1) ? K1OFF : K0OFF);
        const uint32_t vb = su + ((j & 1) ? V1OFF : V0OFF);

        CPWAIT(1);           // j=0: Q+K0 ; j>0: K[j]   (V[j] still streaming)
        __syncthreads();

        // ---- MMA1: S[32 rows][32 jtok] per warp ----
        float S[2][4][4];
        #pragma unroll
        for (int i = 0; i < 2; i++)
            #pragma unroll
            for (int s = 0; s < 4; s++)
                #pragma unroll
                for (int qq = 0; qq < 4; qq++) S[i][s][qq] = 0.f;

        #pragma unroll
        for (int ks = 0; ks < 16; ks++) {
            uint32_t a[2][4];
            #pragma unroll
            for (int i = 0; i < 2; i++)
                ldsm4(a[i], su + QOFF + 2u * (uint32_t)(
                    (wm * 32 + i * 16 + l15) * 264 + ks * 16 + b4 * 8));
            #pragma unroll
            for (int j2 = 0; j2 < 2; j2++) {
                uint32_t bfr[4];
                ldsm4(bfr, kb + 2u * (uint32_t)(
                    (wn * 32 + j2 * 16 + b4 * 8 + l7) * 264 + ks * 16 + b3 * 8));
                #pragma unroll
                for (int i = 0; i < 2; i++) {
                    mma16(S[i][2*j2],     a[i], bfr[0], bfr[1]);
                    mma16(S[i][2*j2 + 1], a[i], bfr[2], bfr[3]);
                }
            }
        }

        // ---- exp2 -> P smem + row-sum partials (log2e folded into q) ----
        #pragma unroll
        for (int i = 0; i < 2; i++) {
            int ml = wm * 32 + i * 16 + g;
            #pragma unroll
            for (int s = 0; s < 4; s++) {
                int nl = wn * 32 + s * 8 + 2 * t;
                float e0 = exp2f(S[i][s][0]);
                float e1 = exp2f(S[i][s][1]);
                float e2 = exp2f(S[i][s][2]);
                float e3 = exp2f(S[i][s][3]);
                rs[i][0] += e0 + e1;
                rs[i][1] += e2 + e3;
                *(__nv_bfloat162*)(Ps + ml * 72 + nl)       = __floats2bfloat162_rn(e0, e1);
                *(__nv_bfloat162*)(Ps + (ml + 8) * 72 + nl) = __floats2bfloat162_rn(e2, e3);
            }
        }
        __syncthreads();     // P written; K[j] reads done

        if (j < 63) {
            stage64((j & 1) ? K0OFF : K1OFF, k, j + 1);
            CPCOMMIT;        // pending: {V[j], K[j+1]}
            CPWAIT(1);       // completes V[j]
        } else {
            CPWAIT(0);       // completes V[63]
        }
        __syncthreads();     // V[j] visible

        // ---- MMA2: O[32 rows][128 ch] += P · V ----
        #pragma unroll
        for (int ks2 = 0; ks2 < 4; ks2++) {
            uint32_t pa[2][4];
            #pragma unroll
            for (int i = 0; i < 2; i++)
                ldsm4(pa[i], su + POFF + 2u * (uint32_t)(
                    (wm * 32 + i * 16 + l15) * 72 + ks2 * 16 + b4 * 8));
            #pragma unroll
            for (int j2 = 0; j2 < 8; j2++) {
                uint32_t bfr[4];
                ldsm4t(bfr, vb + 2u * (uint32_t)(
                    (ks2 * 16 + b3 * 8 + l7) * 264 + wn * 128 + j2 * 16 + b4 * 8));
                #pragma unroll
                for (int i = 0; i < 2; i++) {
                    mma16(O[i][2*j2],     pa[i], bfr[0], bfr[1]);
                    mma16(O[i][2*j2 + 1], pa[i], bfr[2], bfr[3]);
                }
            }
        }

        if (j < 63) {
            stage64((j & 1) ? V0OFF : V1OFF, vt, j + 1);
            CPCOMMIT;        // pending: {K[j+1], V[j+1]}
        } else {
            stageWo();       // all K/V buffers dead
            CPCOMMIT;        // pending: {Wo}
        }
    }

    // ---- row sums -> inverse ----
    float* ps = (float*)(smem + SUMOFF);
    #pragma unroll
    for (int i = 0; i < 2; i++) {
        float s0 = rs[i][0], s1 = rs[i][1];
        s0 += __shfl_xor_sync(0xffffffffu, s0, 1);
        s0 += __shfl_xor_sync(0xffffffffu, s0, 2);
        s1 += __shfl_xor_sync(0xffffffffu, s1, 1);
        s1 += __shfl_xor_sync(0xffffffffu, s1, 2);
        if (t == 0) {
            int r = wm * 32 + i * 16 + g;
            ps[wn * 128 + r]     = s0;
            ps[wn * 128 + r + 8] = s1;
        }
    }
    __syncthreads();
    if (tid < 128) ps[tid] = 1.f / (ps[tid] + ps[128 + tid]);
    __syncthreads();

    // ---- normalize O into Q region ----
    bf16* Os = (bf16*)smem;
    #pragma unroll
    for (int i = 0; i < 2; i++) {
        int r0 = wm * 32 + i * 16 + g;
        int r1 = r0 + 8;
        float iv0 = ps[r0];
        float iv1 = ps[r1];
        #pragma unroll
        for (int b = 0; b < 16; b++) {
            int col = wn * 128 + b * 8 + 2 * t;
            *(__nv_bfloat162*)(Os + r0 * 264 + col) =
                __floats2bfloat162_rn(O[i][b][0] * iv0, O[i][b][1] * iv0);
            *(__nv_bfloat162*)(Os + r1 * 264 + col) =
                __floats2bfloat162_rn(O[i][b][2] * iv1, O[i][b][3] * iv1);
        }
    }
    CPWAIT(0);
    __syncthreads();

    // ---- epilogue GEMM: out[256 co][128 tok] = Wo · Os^T + bo + x ----
    float acc[2][16][4];
    #pragma unroll
    for (int i = 0; i < 2; i++)
        #pragma unroll
        for (int b = 0; b < 16; b++)
            #pragma unroll
            for (int qq = 0; qq < 4; qq++) acc[i][b][qq] = 0.f;

    const uint32_t bases[4] = {K0OFF, K1OFF, V0OFF, V1OFF};
    const uint32_t wo_off = bases[wid >> 1] + (uint32_t)((wid & 1) * 32) * 528;

    #pragma unroll
    for (int ks = 0; ks < 16; ks++) {
        uint32_t a2[2][4];
        #pragma unroll
        for (int i = 0; i < 2; i++)
            ldsm4(a2[i], su + wo_off + 2u * (uint32_t)(
                (i * 16 + l15) * 264 + ks * 16 + b4 * 8));
        #pragma unroll
        for (int j2 = 0; j2 < 8; j2++) {
            uint32_t bfr[4];
            ldsm4(bfr, su + QOFF + 2u * (uint32_t)(
                (j2 * 16 + b4 * 8 + l7) * 264 + ks * 16 + b3 * 8));
            #pragma unroll
            for (int i = 0; i < 2; i++) {
                mma16(acc[i][2*j2],     a2[i], bfr[0], bfr[1]);
                mma16(acc[i][2*j2 + 1], a2[i], bfr[2], bfr[3]);
            }
        }
    }

    #pragma unroll
    for (int i = 0; i < 2; i++) {
        int m = wid * 32 + i * 16 + g;
        float bm0 = bo[m];
        float bm1 = bo[m + 8];
        #pragma unroll
        for (int b = 0; b < 16; b++) {
            int n = i0 + b * 8 + 2 * t;
            float2 x0 = *(const float2*)(x + (size_t)m * NTOK + n);
            float2 x1 = *(const float2*)(x + (size_t)(m + 8) * NTOK + n);
            float2 v0, v1;
            v0.x = acc[i][b][0] + bm0 + x0.x;
            v0.y = acc[i][b][1] + bm0 + x0.y;
            v1.x = acc[i][b][2] + bm1 + x1.x;
            v1.y = acc[i][b][3] + bm1 + x1.y;
            *(float2*)(out + (size_t)m * NTOK + n)       = v0;
            *(float2*)(out + (size_t)(m + 8) * NTOK + n) = v1;
        }
    }
}

// ---------------------------------------------------------------------------
extern "C" void kernel_launch(void* const* d_in, const int* in_sizes, int n_in,
                              void* d_out, int out_size) {
    const float* x    = (const float*)d_in[0];
    const float* gn_w = (const float*)d_in[1];
    const float* gn_b = (const float*)d_in[2];
    const float* wq   = (const float*)d_in[3];
    const float* bq   = (const float*)d_in[4];
    const float* wk   = (const float*)d_in[5];
    const float* bk   = (const float*)d_in[6];
    const float* wv   = (const float*)d_in[7];
    const float* bv   = (const float*)d_in[8];
    const float* wo   = (const float*)d_in[9];
    const float* bo   = (const float*)d_in[10];
    float* out = (float*)d_out;

    void *p_xn, *p_qkv, *p_w, *p_bias, *p_stat;
    cudaGetSymbolAddress(&p_xn,   g_xnb4);
    cudaGetSymbolAddress(&p_qkv,  g_qkvb4);
    cudaGetSymbolAddress(&p_w,    g_wb4);
    cudaGetSymbolAddress(&p_bias, g_biasqkv);
    cudaGetSymbolAddress(&p_stat, g_gnstat);

    bf16* xnb  = (bf16*)p_xn;
    bf16* qkvb = (bf16*)p_qkv;
    bf16* wqb  = (bf16*)p_w;
    bf16* wob  = wqb + 3 * CCH * CCH;
    float* biasqkv = (float*)p_bias;
    float* stat = (float*)p_stat;

    const size_t SBb = (size_t)CCH * NTOK;
    bf16* qb  = qkvb;
    bf16* kb  = qkvb + BATCH * SBb;
    bf16* vtb = qkvb + 2 * BATCH * SBb;

    cudaFuncSetAttribute(bgemm_qkv, cudaFuncAttributeMaxDynamicSharedMemorySize, SMEM_DYN);
    cudaFuncSetAttribute(fattn, cudaFuncAttributeMaxDynamicSharedMemorySize, FSMEM);

    // 0) convert+pack weights / biases
    convw_kernel<<<256, 256>>>(wq, wk, wv, wo, bq, bk, bv,
                               wqb, wqb + CCH*CCH, wqb + 2*CCH*CCH, wob, biasqkv);

    // 1) GroupNorm (stats + apply), bf16 out [c][tok]
    gn_stats_kernel<<<BATCH * GROUPS * 4, 256>>>(x, stat);
    gn_apply_kernel<<<BATCH * GROUPS * 4, 256>>>(x, stat, gn_w, gn_b, xnb);

    // 2) q,k,v transposed projections -> [tok][ch] bf16 (q scaled log2e/16)
    bgemm_qkv<<<dim3(CCH/128, 96, BATCH), 128, SMEM_DYN>>>(
        xnb, wqb, biasqkv, qkvb, NTOK, SBb);

    // 3) fused attention + output projection + residual -> out fp32
    fattn<<<dim3(NTOK/128, BATCH), 256, FSMEM>>>(qb, kb, vtb, wob, bo, x, out);
}